// round 1
// baseline (speedup 1.0000x reference)
#include <cuda_runtime.h>
#include <math.h>
#include <stdint.h>

// ---------------- problem constants ----------------
#define B_   8
#define S_   64
#define N_   1024
#define C_   16
#define H_   128
#define P_   10           // integration points
#define ROWS (B_ * N_)    // 8192 state rows
#define DT_  7.0f         // linspace(0,63,10) spacing, exact in fp32

#define PRED_ELEMS   (B_ * S_ * N_ * C_)       // 8388608
#define INTERP_ELEMS (S_ * B_ * N_ * H_)       // 67108864

// ---------------- device scratch (no allocation allowed) ----------------
__device__ float g_sol[P_ * ROWS * H_];   // trajectory, ~42MB
__device__ float g_dyn[ROWS * H_];        // dyn(s) per step
__device__ float g_logits[ROWS];          // attention logits
__device__ float g_attn[ROWS];            // softmax weights
__device__ int   g_nbr[N_ * N_];          // padded neighbor lists
__device__ int   g_cnt[N_];               // neighbor counts
__device__ float g_invdeg[N_];            // 1/(rowsum+1e-8)

// ---------------- helpers ----------------
__device__ __forceinline__ float sigmoidf_(float v) { return 1.0f / (1.0f + __expf(-v)); }
__device__ __forceinline__ float siluf_(float v)    { return v * sigmoidf_(v); }
__device__ __forceinline__ float sanf_(float v) {
    if (isnan(v)) return 0.0f;
    if (isinf(v)) return v > 0.0f ? 3.402823466e38f : -3.402823466e38f;
    return v;
}

// block-wide sum for 128 threads (4 warps). red must hold >= 4 floats.
__device__ __forceinline__ float blk_sum128(float v, float* red) {
    #pragma unroll
    for (int o = 16; o > 0; o >>= 1) v += __shfl_down_sync(0xffffffffu, v, o);
    __syncthreads();                       // protect red from previous use
    if ((threadIdx.x & 31) == 0) red[threadIdx.x >> 5] = v;
    __syncthreads();
    return red[0] + red[1] + red[2] + red[3];
}

// ---------------- kernel 1: normalized adjacency -> neighbor lists ----------------
// 1024 blocks, 32 threads (one warp per row). Deterministic ballot compaction.
__global__ void build_graph_kernel(const float* __restrict__ adj) {
    int m = blockIdx.x;
    int l = threadIdx.x;
    float deg = 0.0f;
    int cnt = 0;
    for (int base = 0; base < N_; base += 32) {
        float a = adj[m * N_ + base + l];
        bool nz = (a != 0.0f);
        deg += a;
        unsigned mask = __ballot_sync(0xffffffffu, nz);
        int pre = __popc(mask & ((1u << l) - 1u));
        if (nz) g_nbr[m * N_ + cnt + pre] = base + l;
        cnt += __popc(mask);
    }
    #pragma unroll
    for (int o = 16; o > 0; o >>= 1) deg += __shfl_down_sync(0xffffffffu, deg, o);
    if (l == 0) {
        g_cnt[m] = cnt;
        g_invdeg[m] = 1.0f / (deg + 1e-8f);
    }
}

// ---------------- kernel 2: encoder -> sol[0] ----------------
// 8192 blocks x 128 threads. z0 = silu(LN(x[:,0] @ enc_w + enc_b))
__global__ __launch_bounds__(128) void encoder_kernel(
    const float* __restrict__ x, const float* __restrict__ enc_w,
    const float* __restrict__ enc_b, const float* __restrict__ enc_g,
    const float* __restrict__ enc_beta)
{
    int row = blockIdx.x;                 // b*N + n
    int b = row >> 10, n = row & 1023;
    int j = threadIdx.x;
    __shared__ float xr[C_];
    __shared__ float red[4];
    if (j < C_) xr[j] = x[(size_t)b * (S_ * N_ * C_) + (size_t)n * C_ + j];
    __syncthreads();
    float acc = enc_b[j];
    #pragma unroll
    for (int c = 0; c < C_; ++c) acc = fmaf(xr[c], enc_w[c * H_ + j], acc);
    float mean = blk_sum128(acc, red) * (1.0f / H_);
    float d = acc - mean;
    float var = blk_sum128(d * d, red) * (1.0f / H_);
    float yn = d * rsqrtf(var + 1e-5f) * enc_g[j] + enc_beta[j];
    g_sol[(size_t)row * H_ + j] = siluf_(yn);
}

// ---------------- kernel 3: per-step dyn MLP + attention logit ----------------
__global__ __launch_bounds__(128) void step_dyn_kernel(
    int p,
    const float* __restrict__ w1, const float* __restrict__ b1,
    const float* __restrict__ lg, const float* __restrict__ lb,
    const float* __restrict__ w2, const float* __restrict__ b2,
    const float* __restrict__ attn_w, const float* __restrict__ attn_b)
{
    int row = blockIdx.x;
    int j = threadIdx.x;
    __shared__ float sr[H_];
    __shared__ float h1[H_];
    __shared__ float red[4];

    float sv = sanf_(g_sol[(size_t)p * ROWS * H_ + (size_t)row * H_ + j]);
    sr[j] = sv;
    __syncthreads();

    // attention logit: dot(s, attn_w) + attn_b
    float lgt = blk_sum128(sv * attn_w[j], red);
    if (j == 0) g_logits[row] = lgt + attn_b[0];

    // h1 = silu(LN(s @ w1 + b1))
    float acc = b1[j];
    const float4* sr4 = reinterpret_cast<const float4*>(sr);
    #pragma unroll 8
    for (int k4 = 0; k4 < H_ / 4; ++k4) {
        float4 v = sr4[k4];
        const float* wp = &w1[(k4 * 4) * H_ + j];
        acc = fmaf(v.x, wp[0],       acc);
        acc = fmaf(v.y, wp[H_],      acc);
        acc = fmaf(v.z, wp[2 * H_],  acc);
        acc = fmaf(v.w, wp[3 * H_],  acc);
    }
    float mean = blk_sum128(acc, red) * (1.0f / H_);
    float d = acc - mean;
    float var = blk_sum128(d * d, red) * (1.0f / H_);
    float yn = d * rsqrtf(var + 1e-5f) * lg[j] + lb[j];
    h1[j] = siluf_(yn);
    __syncthreads();

    // dyn = tanh(h1 @ w2 + b2)
    float a2 = b2[j];
    const float4* h4 = reinterpret_cast<const float4*>(h1);
    #pragma unroll 8
    for (int k4 = 0; k4 < H_ / 4; ++k4) {
        float4 v = h4[k4];
        const float* wp = &w2[(k4 * 4) * H_ + j];
        a2 = fmaf(v.x, wp[0],       a2);
        a2 = fmaf(v.y, wp[H_],      a2);
        a2 = fmaf(v.z, wp[2 * H_],  a2);
        a2 = fmaf(v.w, wp[3 * H_],  a2);
    }
    g_dyn[(size_t)row * H_ + j] = tanhf(a2);
}

// ---------------- kernel 4: softmax over nodes per batch ----------------
// 8 blocks x 256 threads
__global__ __launch_bounds__(256) void softmax_kernel() {
    int b = blockIdx.x;
    int t = threadIdx.x;
    __shared__ float red[8];
    const float* lg = &g_logits[b * N_];

    float m = -INFINITY;
    for (int n = t; n < N_; n += 256) m = fmaxf(m, lg[n]);
    #pragma unroll
    for (int o = 16; o > 0; o >>= 1) m = fmaxf(m, __shfl_down_sync(0xffffffffu, m, o));
    if ((t & 31) == 0) red[t >> 5] = m;
    __syncthreads();
    float mx = red[0];
    #pragma unroll
    for (int w = 1; w < 8; ++w) mx = fmaxf(mx, red[w]);
    __syncthreads();

    float ssum = 0.0f;
    for (int n = t; n < N_; n += 256) ssum += expf(lg[n] - mx);
    #pragma unroll
    for (int o = 16; o > 0; o >>= 1) ssum += __shfl_down_sync(0xffffffffu, ssum, o);
    if ((t & 31) == 0) red[t >> 5] = ssum;
    __syncthreads();
    float tot = 0.0f;
    #pragma unroll
    for (int w = 0; w < 8; ++w) tot += red[w];
    float inv = 1.0f / tot;

    for (int n = t; n < N_; n += 256)
        g_attn[b * N_ + n] = expf(lg[n] - mx) * inv;
}

// ---------------- kernel 5: diffusion gather + clamp + Euler update ----------------
__global__ __launch_bounds__(128) void step_update_kernel(
    int p, const float* __restrict__ diff_scale, const float* __restrict__ time_scale)
{
    int row = blockIdx.x;
    int b = row >> 10, m = row & 1023;
    int j = threadIdx.x;
    __shared__ float attn_sh[N_];
    __shared__ float red[4];

    for (int i = j; i < N_; i += 128) attn_sh[i] = g_attn[b * N_ + i];
    __syncthreads();

    int cnt = g_cnt[m];
    const int* nb = &g_nbr[m * N_];
    const float* sbase = &g_sol[(size_t)p * ROWS * H_ + (size_t)b * N_ * H_];
    float diff = 0.0f;
    for (int i = 0; i < cnt; ++i) {
        int n = nb[i];
        diff = fmaf(sanf_(sbase[(size_t)n * H_ + j]), attn_sh[n], diff);
    }
    diff *= g_invdeg[m] * diff_scale[0];

    float dyn = g_dyn[(size_t)row * H_ + j];
    float dx = time_scale[0] * (dyn + diff);
    float n2 = blk_sum128(dx * dx, red);
    float nrm = sqrtf(n2);
    float sc = fminf(10.0f / (nrm + 1e-8f), 1.0f);
    dx = sanf_(dx * sc);

    float sold = g_sol[(size_t)p * ROWS * H_ + (size_t)row * H_ + j];
    g_sol[(size_t)(p + 1) * ROWS * H_ + (size_t)row * H_ + j] = sold + dx * DT_;
}

// ---------------- kernel 6: interp + decoder ----------------
// 524288 blocks x 128 threads. interp row -> interp out; decoder MLP -> pred out.
__global__ __launch_bounds__(128) void decoder_kernel(
    const float* __restrict__ w1, const float* __restrict__ b1,
    const float* __restrict__ lg, const float* __restrict__ lb,
    const float* __restrict__ w2, const float* __restrict__ b2,
    float* __restrict__ out_pred, float* __restrict__ out_interp)
{
    int row = blockIdx.x;                   // (s*B + b)*N + n
    int n = row & 1023;
    int sb = row >> 10;
    int b = sb & 7;
    int s = sb >> 3;
    int j = threadIdx.x;

    int ic = (s + 6) / 7;
    if (ic < 1) ic = 1;
    if (ic > P_ - 1) ic = P_ - 1;
    float alpha = (float)(s - 7 * (ic - 1)) * (1.0f / 7.0f);

    size_t base = ((size_t)b * N_ + n) * H_;
    float v0 = g_sol[(size_t)(ic - 1) * ROWS * H_ + base + j];
    float v1 = g_sol[(size_t)ic * ROWS * H_ + base + j];
    float iv = (1.0f - alpha) * v0 + alpha * v1;

    __shared__ float ir[H_];
    __shared__ float h[H_];
    __shared__ float red[4];
    ir[j] = iv;
    if (out_interp) out_interp[(size_t)row * H_ + j] = iv;
    __syncthreads();

    // h = silu(LN(interp @ dec_w1 + dec_b1))
    float acc = b1[j];
    const float4* ir4 = reinterpret_cast<const float4*>(ir);
    #pragma unroll 8
    for (int k4 = 0; k4 < H_ / 4; ++k4) {
        float4 v = ir4[k4];
        const float* wp = &w1[(k4 * 4) * H_ + j];
        acc = fmaf(v.x, wp[0],       acc);
        acc = fmaf(v.y, wp[H_],      acc);
        acc = fmaf(v.z, wp[2 * H_],  acc);
        acc = fmaf(v.w, wp[3 * H_],  acc);
    }
    float mean = blk_sum128(acc, red) * (1.0f / H_);
    float d = acc - mean;
    float var = blk_sum128(d * d, red) * (1.0f / H_);
    float yn = d * rsqrtf(var + 1e-5f) * lg[j] + lb[j];
    h[j] = siluf_(yn);
    __syncthreads();

    // pred = h @ dec_w2 + dec_b2 ; warp w handles output cols 4w..4w+3
    if (out_pred) {
        int w = j >> 5, l = j & 31;
        #pragma unroll
        for (int cc = 0; cc < 4; ++cc) {
            int c = w * 4 + cc;
            float pacc = 0.0f;
            #pragma unroll
            for (int k = l; k < H_; k += 32) pacc = fmaf(h[k], w2[k * C_ + c], pacc);
            #pragma unroll
            for (int o = 16; o > 0; o >>= 1) pacc += __shfl_down_sync(0xffffffffu, pacc, o);
            if (l == 0)
                out_pred[(((size_t)b * S_ + s) * N_ + n) * C_ + c] = pacc + b2[c];
        }
    }
}

// ---------------- launch ----------------
extern "C" void kernel_launch(void* const* d_in, const int* in_sizes, int n_in,
                              void* d_out, int out_size)
{
    const float* x        = (const float*)d_in[0];
    const float* adj      = (const float*)d_in[1];
    const float* enc_w    = (const float*)d_in[2];
    const float* enc_b    = (const float*)d_in[3];
    const float* enc_g    = (const float*)d_in[4];
    const float* enc_beta = (const float*)d_in[5];
    const float* dyn_w1   = (const float*)d_in[6];
    const float* dyn_b1   = (const float*)d_in[7];
    const float* dyn_g    = (const float*)d_in[8];
    const float* dyn_beta = (const float*)d_in[9];
    const float* dyn_w2   = (const float*)d_in[10];
    const float* dyn_b2   = (const float*)d_in[11];
    const float* attn_w   = (const float*)d_in[12];
    const float* attn_b   = (const float*)d_in[13];
    const float* diff_sc  = (const float*)d_in[14];
    const float* time_sc  = (const float*)d_in[15];
    const float* dec_w1   = (const float*)d_in[16];
    const float* dec_b1   = (const float*)d_in[17];
    const float* dec_g    = (const float*)d_in[18];
    const float* dec_beta = (const float*)d_in[19];
    const float* dec_w2   = (const float*)d_in[20];
    const float* dec_b2   = (const float*)d_in[21];

    float* out = (float*)d_out;
    float* out_pred = nullptr;
    float* out_interp = nullptr;
    if (out_size >= PRED_ELEMS + INTERP_ELEMS) {
        out_pred = out;
        out_interp = out + PRED_ELEMS;
    } else if (out_size == PRED_ELEMS) {
        out_pred = out;
    } else if (out_size == INTERP_ELEMS) {
        out_interp = out;
    } else {
        out_pred = out;   // best effort
    }

    build_graph_kernel<<<N_, 32>>>(adj);
    encoder_kernel<<<ROWS, 128>>>(x, enc_w, enc_b, enc_g, enc_beta);

    for (int p = 0; p < P_ - 1; ++p) {
        step_dyn_kernel<<<ROWS, 128>>>(p, dyn_w1, dyn_b1, dyn_g, dyn_beta,
                                       dyn_w2, dyn_b2, attn_w, attn_b);
        softmax_kernel<<<B_, 256>>>();
        step_update_kernel<<<ROWS, 128>>>(p, diff_sc, time_sc);
    }

    decoder_kernel<<<S_ * B_ * N_, 128>>>(dec_w1, dec_b1, dec_g, dec_beta,
                                          dec_w2, dec_b2, out_pred, out_interp);
}

// round 2
// speedup vs baseline: 2.7709x; 2.7709x over previous
#include <cuda_runtime.h>
#include <math.h>
#include <stdint.h>

// ---------------- problem constants ----------------
#define B_   8
#define S_   64
#define N_   1024
#define C_   16
#define H_   128
#define P_   10           // integration points
#define ROWS (B_ * N_)    // 8192 state rows
#define DT_  7.0f         // linspace(0,63,10) spacing, exact in fp32

#define PRED_ELEMS   (B_ * S_ * N_ * C_)       // 8388608
#define INTERP_ELEMS (S_ * B_ * N_ * H_)       // 67108864

// ---------------- device scratch (no allocation allowed) ----------------
__device__ float g_sol[P_ * ROWS * H_];   // trajectory, ~42MB
__device__ float g_dyn[ROWS * H_];        // dyn(s) per step
__device__ float g_logits[ROWS];          // attention logits
__device__ float g_attn[ROWS];            // softmax weights
__device__ int   g_nbr[N_ * N_];          // padded neighbor lists
__device__ int   g_cnt[N_];               // neighbor counts
__device__ float g_invdeg[N_];            // 1/(rowsum+1e-8)

// ---------------- helpers ----------------
__device__ __forceinline__ float sigmoidf_(float v) { return 1.0f / (1.0f + __expf(-v)); }
__device__ __forceinline__ float siluf_(float v)    { return v * sigmoidf_(v); }
__device__ __forceinline__ float sanf_(float v) {
    if (isnan(v)) return 0.0f;
    if (isinf(v)) return v > 0.0f ? 3.402823466e38f : -3.402823466e38f;
    return v;
}

// block-wide sum for 128 threads (4 warps). red must hold >= 4 floats.
__device__ __forceinline__ float blk_sum128(float v, float* red) {
    #pragma unroll
    for (int o = 16; o > 0; o >>= 1) v += __shfl_down_sync(0xffffffffu, v, o);
    __syncthreads();                       // protect red from previous use
    if ((threadIdx.x & 31) == 0) red[threadIdx.x >> 5] = v;
    __syncthreads();
    return red[0] + red[1] + red[2] + red[3];
}

// ---------------- kernel 1: normalized adjacency -> neighbor lists ----------------
__global__ void build_graph_kernel(const float* __restrict__ adj) {
    int m = blockIdx.x;
    int l = threadIdx.x;
    float deg = 0.0f;
    int cnt = 0;
    for (int base = 0; base < N_; base += 32) {
        float a = adj[m * N_ + base + l];
        bool nz = (a != 0.0f);
        deg += a;
        unsigned mask = __ballot_sync(0xffffffffu, nz);
        int pre = __popc(mask & ((1u << l) - 1u));
        if (nz) g_nbr[m * N_ + cnt + pre] = base + l;
        cnt += __popc(mask);
    }
    #pragma unroll
    for (int o = 16; o > 0; o >>= 1) deg += __shfl_down_sync(0xffffffffu, deg, o);
    if (l == 0) {
        g_cnt[m] = cnt;
        g_invdeg[m] = 1.0f / (deg + 1e-8f);
    }
}

// ---------------- kernel 2: encoder -> sol[0] ----------------
__global__ __launch_bounds__(128) void encoder_kernel(
    const float* __restrict__ x, const float* __restrict__ enc_w,
    const float* __restrict__ enc_b, const float* __restrict__ enc_g,
    const float* __restrict__ enc_beta)
{
    int row = blockIdx.x;                 // b*N + n
    int b = row >> 10, n = row & 1023;
    int j = threadIdx.x;
    __shared__ float xr[C_];
    __shared__ float red[4];
    if (j < C_) xr[j] = x[(size_t)b * (S_ * N_ * C_) + (size_t)n * C_ + j];
    __syncthreads();
    float acc = enc_b[j];
    #pragma unroll
    for (int c = 0; c < C_; ++c) acc = fmaf(xr[c], enc_w[c * H_ + j], acc);
    float mean = blk_sum128(acc, red) * (1.0f / H_);
    float d = acc - mean;
    float var = blk_sum128(d * d, red) * (1.0f / H_);
    float yn = d * rsqrtf(var + 1e-5f) * enc_g[j] + enc_beta[j];
    g_sol[(size_t)row * H_ + j] = siluf_(yn);
}

// ---------------- kernel 3: per-step dyn MLP + attention logit ----------------
__global__ __launch_bounds__(128) void step_dyn_kernel(
    int p,
    const float* __restrict__ w1, const float* __restrict__ b1,
    const float* __restrict__ lg, const float* __restrict__ lb,
    const float* __restrict__ w2, const float* __restrict__ b2,
    const float* __restrict__ attn_w, const float* __restrict__ attn_b)
{
    int row = blockIdx.x;
    int j = threadIdx.x;
    __shared__ float sr[H_];
    __shared__ float h1[H_];
    __shared__ float red[4];

    float sv = sanf_(g_sol[(size_t)p * ROWS * H_ + (size_t)row * H_ + j]);
    sr[j] = sv;
    __syncthreads();

    float lgt = blk_sum128(sv * attn_w[j], red);
    if (j == 0) g_logits[row] = lgt + attn_b[0];

    float acc = b1[j];
    const float4* sr4 = reinterpret_cast<const float4*>(sr);
    #pragma unroll 8
    for (int k4 = 0; k4 < H_ / 4; ++k4) {
        float4 v = sr4[k4];
        const float* wp = &w1[(k4 * 4) * H_ + j];
        acc = fmaf(v.x, wp[0],       acc);
        acc = fmaf(v.y, wp[H_],      acc);
        acc = fmaf(v.z, wp[2 * H_],  acc);
        acc = fmaf(v.w, wp[3 * H_],  acc);
    }
    float mean = blk_sum128(acc, red) * (1.0f / H_);
    float d = acc - mean;
    float var = blk_sum128(d * d, red) * (1.0f / H_);
    float yn = d * rsqrtf(var + 1e-5f) * lg[j] + lb[j];
    h1[j] = siluf_(yn);
    __syncthreads();

    float a2 = b2[j];
    const float4* h4 = reinterpret_cast<const float4*>(h1);
    #pragma unroll 8
    for (int k4 = 0; k4 < H_ / 4; ++k4) {
        float4 v = h4[k4];
        const float* wp = &w2[(k4 * 4) * H_ + j];
        a2 = fmaf(v.x, wp[0],       a2);
        a2 = fmaf(v.y, wp[H_],      a2);
        a2 = fmaf(v.z, wp[2 * H_],  a2);
        a2 = fmaf(v.w, wp[3 * H_],  a2);
    }
    g_dyn[(size_t)row * H_ + j] = tanhf(a2);
}

// ---------------- kernel 4: softmax over nodes per batch ----------------
__global__ __launch_bounds__(256) void softmax_kernel() {
    int b = blockIdx.x;
    int t = threadIdx.x;
    __shared__ float red[8];
    const float* lg = &g_logits[b * N_];

    float m = -INFINITY;
    for (int n = t; n < N_; n += 256) m = fmaxf(m, lg[n]);
    #pragma unroll
    for (int o = 16; o > 0; o >>= 1) m = fmaxf(m, __shfl_down_sync(0xffffffffu, m, o));
    if ((t & 31) == 0) red[t >> 5] = m;
    __syncthreads();
    float mx = red[0];
    #pragma unroll
    for (int w = 1; w < 8; ++w) mx = fmaxf(mx, red[w]);
    __syncthreads();

    float ssum = 0.0f;
    for (int n = t; n < N_; n += 256) ssum += expf(lg[n] - mx);
    #pragma unroll
    for (int o = 16; o > 0; o >>= 1) ssum += __shfl_down_sync(0xffffffffu, ssum, o);
    if ((t & 31) == 0) red[t >> 5] = ssum;
    __syncthreads();
    float tot = 0.0f;
    #pragma unroll
    for (int w = 0; w < 8; ++w) tot += red[w];
    float inv = 1.0f / tot;

    for (int n = t; n < N_; n += 256)
        g_attn[b * N_ + n] = expf(lg[n] - mx) * inv;
}

// ---------------- kernel 5: diffusion gather + clamp + Euler update ----------------
__global__ __launch_bounds__(128) void step_update_kernel(
    int p, const float* __restrict__ diff_scale, const float* __restrict__ time_scale)
{
    int row = blockIdx.x;
    int b = row >> 10, m = row & 1023;
    int j = threadIdx.x;
    __shared__ float attn_sh[N_];
    __shared__ float red[4];

    for (int i = j; i < N_; i += 128) attn_sh[i] = g_attn[b * N_ + i];
    __syncthreads();

    int cnt = g_cnt[m];
    const int* nb = &g_nbr[m * N_];
    const float* sbase = &g_sol[(size_t)p * ROWS * H_ + (size_t)b * N_ * H_];
    float diff = 0.0f;
    for (int i = 0; i < cnt; ++i) {
        int n = nb[i];
        diff = fmaf(sanf_(sbase[(size_t)n * H_ + j]), attn_sh[n], diff);
    }
    diff *= g_invdeg[m] * diff_scale[0];

    float dyn = g_dyn[(size_t)row * H_ + j];
    float dx = time_scale[0] * (dyn + diff);
    float n2 = blk_sum128(dx * dx, red);
    float nrm = sqrtf(n2);
    float sc = fminf(10.0f / (nrm + 1e-8f), 1.0f);
    dx = sanf_(dx * sc);

    float sold = g_sol[(size_t)p * ROWS * H_ + (size_t)row * H_ + j];
    g_sol[(size_t)(p + 1) * ROWS * H_ + (size_t)row * H_ + j] = sold + dx * DT_;
}

// ---------------- kernel 6: register-tiled interp + decoder GEMM ----------------
// grid = 8192 blocks; block = 64 rows (same (s,b), n contiguous) x 128 cols.
// 128 threads, 8x8 accumulator tile each. smem buf reused: Xt[k][r] then Hs[r][k].
__global__ __launch_bounds__(128) void decoder_gemm_kernel(
    const float* __restrict__ w1, const float* __restrict__ b1,
    const float* __restrict__ lgm, const float* __restrict__ lbt,
    const float* __restrict__ w2, const float* __restrict__ b2,
    float* __restrict__ out_pred, float* __restrict__ out_interp)
{
    __shared__ float buf[64 * 128];        // 32 KB: Xt then Hs
    __shared__ float psum[64 * 16];
    __shared__ float psq[64 * 16];
    __shared__ float s_mean[64];
    __shared__ float s_rstd[64];

    int blk = blockIdx.x;
    int tid = threadIdx.x;
    int n0 = (blk & 15) << 6;              // 16 blocks per (s,b)
    int sb = blk >> 4;
    int b  = sb & 7;
    int s  = sb >> 3;

    // ---- interpolation coefficients (matches round-1 validated formula) ----
    int ic = (s + 6) / 7;
    if (ic < 1) ic = 1;
    if (ic > P_ - 1) ic = P_ - 1;
    float alpha = (float)(s - 7 * (ic - 1)) * (1.0f / 7.0f);

    // ---- load 64x128 interp tile, write out_interp, store transposed Xt[k][r] ----
    {
        int r  = tid >> 1;
        int c0 = (tid & 1) << 6;           // 0 or 64
        size_t rowbase = ((size_t)b * N_ + (n0 + r)) * H_ + c0;
        const float4* p0 = (const float4*)(g_sol + (size_t)(ic - 1) * ROWS * H_ + rowbase);
        const float4* p1 = (const float4*)(g_sol + (size_t)ic * ROWS * H_ + rowbase);
        float4* po = nullptr;
        if (out_interp)
            po = (float4*)(out_interp + ((size_t)(s * B_ + b) * N_ + (n0 + r)) * H_ + c0);
        #pragma unroll
        for (int q = 0; q < 16; ++q) {
            float4 v0 = p0[q], v1 = p1[q];
            float4 iv;
            iv.x = (1.0f - alpha) * v0.x + alpha * v1.x;
            iv.y = (1.0f - alpha) * v0.y + alpha * v1.y;
            iv.z = (1.0f - alpha) * v0.z + alpha * v1.z;
            iv.w = (1.0f - alpha) * v0.w + alpha * v1.w;
            if (po) po[q] = iv;
            int k = c0 + q * 4;
            buf[(k + 0) * 64 + r] = iv.x;
            buf[(k + 1) * 64 + r] = iv.y;
            buf[(k + 2) * 64 + r] = iv.z;
            buf[(k + 3) * 64 + r] = iv.w;
        }
    }
    __syncthreads();

    // ---- GEMM1: acc[8][8], thread (tx,ty): rows ty*8..+7, cols tx*8..+7 ----
    int tx = tid & 15;
    int ty = tid >> 4;
    float acc[8][8];
    {
        float4 bi0 = *(const float4*)(b1 + tx * 8);
        float4 bi1 = *(const float4*)(b1 + tx * 8 + 4);
        #pragma unroll
        for (int i = 0; i < 8; ++i) {
            acc[i][0] = bi0.x; acc[i][1] = bi0.y; acc[i][2] = bi0.z; acc[i][3] = bi0.w;
            acc[i][4] = bi1.x; acc[i][5] = bi1.y; acc[i][6] = bi1.z; acc[i][7] = bi1.w;
        }
    }
    const float4* wv = (const float4*)w1;
    #pragma unroll 4
    for (int k = 0; k < H_; ++k) {
        float4 a0 = *(const float4*)&buf[k * 64 + ty * 8];
        float4 a1 = *(const float4*)&buf[k * 64 + ty * 8 + 4];
        float4 w0 = wv[k * 32 + tx * 2];
        float4 w1v = wv[k * 32 + tx * 2 + 1];
        float av[8] = {a0.x, a0.y, a0.z, a0.w, a1.x, a1.y, a1.z, a1.w};
        float bv[8] = {w0.x, w0.y, w0.z, w0.w, w1v.x, w1v.y, w1v.z, w1v.w};
        #pragma unroll
        for (int i = 0; i < 8; ++i)
            #pragma unroll
            for (int j = 0; j < 8; ++j)
                acc[i][j] = fmaf(av[i], bv[j], acc[i][j]);
    }

    // ---- LN stats: deterministic two-level reduction ----
    #pragma unroll
    for (int i = 0; i < 8; ++i) {
        float sm = 0.0f, sq = 0.0f;
        #pragma unroll
        for (int j = 0; j < 8; ++j) { sm += acc[i][j]; sq = fmaf(acc[i][j], acc[i][j], sq); }
        psum[(ty * 8 + i) * 16 + tx] = sm;
        psq [(ty * 8 + i) * 16 + tx] = sq;
    }
    __syncthreads();
    if (tid < 64) {
        float sm = 0.0f, sq = 0.0f;
        #pragma unroll
        for (int t = 0; t < 16; ++t) { sm += psum[tid * 16 + t]; sq += psq[tid * 16 + t]; }
        float mean = sm * (1.0f / H_);
        float var  = fmaxf(sq * (1.0f / H_) - mean * mean, 0.0f);
        s_mean[tid] = mean;
        s_rstd[tid] = rsqrtf(var + 1e-5f);
    }
    __syncthreads();

    // ---- apply LN + SiLU, write Hs[r][k] (reuse buf; all Xt reads done) ----
    {
        float4 g0 = *(const float4*)(lgm + tx * 8);
        float4 g1 = *(const float4*)(lgm + tx * 8 + 4);
        float4 e0 = *(const float4*)(lbt + tx * 8);
        float4 e1 = *(const float4*)(lbt + tx * 8 + 4);
        float gj[8] = {g0.x, g0.y, g0.z, g0.w, g1.x, g1.y, g1.z, g1.w};
        float ej[8] = {e0.x, e0.y, e0.z, e0.w, e1.x, e1.y, e1.z, e1.w};
        #pragma unroll
        for (int i = 0; i < 8; ++i) {
            int r = ty * 8 + i;
            float m = s_mean[r], rs = s_rstd[r];
            float hv[8];
            #pragma unroll
            for (int j = 0; j < 8; ++j) {
                float yn = (acc[i][j] - m) * rs * gj[j] + ej[j];
                hv[j] = siluf_(yn);
            }
            float4* dst = (float4*)&buf[r * 128 + tx * 8];
            dst[0] = make_float4(hv[0], hv[1], hv[2], hv[3]);
            dst[1] = make_float4(hv[4], hv[5], hv[6], hv[7]);
        }
    }
    __syncthreads();

    // ---- GEMM2: pred[64 x 16]. thread: c0=(tid&3)*4 cols, rows rg*2..+1 ----
    if (out_pred) {
        int c0 = (tid & 3) * 4;
        int rg = tid >> 2;                 // 0..31 -> rows rg*2, rg*2+1
        float4 bb = *(const float4*)(b2 + c0);
        float acc2[2][4];
        #pragma unroll
        for (int r = 0; r < 2; ++r) {
            acc2[r][0] = bb.x; acc2[r][1] = bb.y; acc2[r][2] = bb.z; acc2[r][3] = bb.w;
        }
        #pragma unroll 4
        for (int k4 = 0; k4 < 32; ++k4) {
            int k = k4 * 4;
            float4 wr0 = *(const float4*)(w2 + (k + 0) * C_ + c0);
            float4 wr1 = *(const float4*)(w2 + (k + 1) * C_ + c0);
            float4 wr2 = *(const float4*)(w2 + (k + 2) * C_ + c0);
            float4 wr3 = *(const float4*)(w2 + (k + 3) * C_ + c0);
            #pragma unroll
            for (int r = 0; r < 2; ++r) {
                float4 av = *(const float4*)&buf[(rg * 2 + r) * 128 + k];
                acc2[r][0] = fmaf(av.x, wr0.x, acc2[r][0]);
                acc2[r][1] = fmaf(av.x, wr0.y, acc2[r][1]);
                acc2[r][2] = fmaf(av.x, wr0.z, acc2[r][2]);
                acc2[r][3] = fmaf(av.x, wr0.w, acc2[r][3]);
                acc2[r][0] = fmaf(av.y, wr1.x, acc2[r][0]);
                acc2[r][1] = fmaf(av.y, wr1.y, acc2[r][1]);
                acc2[r][2] = fmaf(av.y, wr1.z, acc2[r][2]);
                acc2[r][3] = fmaf(av.y, wr1.w, acc2[r][3]);
                acc2[r][0] = fmaf(av.z, wr2.x, acc2[r][0]);
                acc2[r][1] = fmaf(av.z, wr2.y, acc2[r][1]);
                acc2[r][2] = fmaf(av.z, wr2.z, acc2[r][2]);
                acc2[r][3] = fmaf(av.z, wr2.w, acc2[r][3]);
                acc2[r][0] = fmaf(av.w, wr3.x, acc2[r][0]);
                acc2[r][1] = fmaf(av.w, wr3.y, acc2[r][1]);
                acc2[r][2] = fmaf(av.w, wr3.z, acc2[r][2]);
                acc2[r][3] = fmaf(av.w, wr3.w, acc2[r][3]);
            }
        }
        #pragma unroll
        for (int r = 0; r < 2; ++r) {
            int n = n0 + rg * 2 + r;
            float4* dst = (float4*)&out_pred[(((size_t)b * S_ + s) * N_ + n) * C_ + c0];
            *dst = make_float4(acc2[r][0], acc2[r][1], acc2[r][2], acc2[r][3]);
        }
    }
}

// ---------------- launch ----------------
extern "C" void kernel_launch(void* const* d_in, const int* in_sizes, int n_in,
                              void* d_out, int out_size)
{
    const float* x        = (const float*)d_in[0];
    const float* adj      = (const float*)d_in[1];
    const float* enc_w    = (const float*)d_in[2];
    const float* enc_b    = (const float*)d_in[3];
    const float* enc_g    = (const float*)d_in[4];
    const float* enc_beta = (const float*)d_in[5];
    const float* dyn_w1   = (const float*)d_in[6];
    const float* dyn_b1   = (const float*)d_in[7];
    const float* dyn_g    = (const float*)d_in[8];
    const float* dyn_beta = (const float*)d_in[9];
    const float* dyn_w2   = (const float*)d_in[10];
    const float* dyn_b2   = (const float*)d_in[11];
    const float* attn_w   = (const float*)d_in[12];
    const float* attn_b   = (const float*)d_in[13];
    const float* diff_sc  = (const float*)d_in[14];
    const float* time_sc  = (const float*)d_in[15];
    const float* dec_w1   = (const float*)d_in[16];
    const float* dec_b1   = (const float*)d_in[17];
    const float* dec_g    = (const float*)d_in[18];
    const float* dec_beta = (const float*)d_in[19];
    const float* dec_w2   = (const float*)d_in[20];
    const float* dec_b2   = (const float*)d_in[21];

    float* out = (float*)d_out;
    float* out_pred = nullptr;
    float* out_interp = nullptr;
    if (out_size >= PRED_ELEMS + INTERP_ELEMS) {
        out_pred = out;
        out_interp = out + PRED_ELEMS;
    } else if (out_size == PRED_ELEMS) {
        out_pred = out;
    } else if (out_size == INTERP_ELEMS) {
        out_interp = out;
    } else {
        out_pred = out;   // best effort
    }

    build_graph_kernel<<<N_, 32>>>(adj);
    encoder_kernel<<<ROWS, 128>>>(x, enc_w, enc_b, enc_g, enc_beta);

    for (int p = 0; p < P_ - 1; ++p) {
        step_dyn_kernel<<<ROWS, 128>>>(p, dyn_w1, dyn_b1, dyn_g, dyn_beta,
                                       dyn_w2, dyn_b2, attn_w, attn_b);
        softmax_kernel<<<B_, 256>>>();
        step_update_kernel<<<ROWS, 128>>>(p, diff_sc, time_sc);
    }

    decoder_gemm_kernel<<<S_ * B_ * N_ / 64, 128>>>(dec_w1, dec_b1, dec_g, dec_beta,
                                                    dec_w2, dec_b2, out_pred, out_interp);
}

// round 3
// speedup vs baseline: 3.1519x; 1.1375x over previous
#include <cuda_runtime.h>
#include <math.h>
#include <stdint.h>

// ---------------- problem constants ----------------
#define B_   8
#define S_   64
#define N_   1024
#define C_   16
#define H_   128
#define P_   10
#define ROWS (B_ * N_)    // 8192
#define DT_  7.0f

#define PRED_ELEMS   (B_ * S_ * N_ * C_)       // 8388608
#define INTERP_ELEMS (S_ * B_ * N_ * H_)       // 67108864

// ---------------- device scratch ----------------
__device__ float g_sol[P_ * ROWS * H_];   // trajectory ~42MB
__device__ float g_y[P_ * ROWS * H_];     // sol@dec_w1+b1 per frame ~42MB
__device__ float g_dyn[ROWS * H_];
__device__ float g_logits[ROWS];
__device__ int   g_nbr[N_ * N_];
__device__ int   g_cnt[N_];
__device__ float g_invdeg[N_];

// ---------------- helpers ----------------
__device__ __forceinline__ float sigmoidf_(float v) { return 1.0f / (1.0f + __expf(-v)); }
__device__ __forceinline__ float siluf_(float v)    { return v * sigmoidf_(v); }
__device__ __forceinline__ float sanf_(float v) {
    if (isnan(v)) return 0.0f;
    if (isinf(v)) return v > 0.0f ? 3.402823466e38f : -3.402823466e38f;
    return v;
}

__device__ __forceinline__ float blk_sum128(float v, float* red) {
    #pragma unroll
    for (int o = 16; o > 0; o >>= 1) v += __shfl_down_sync(0xffffffffu, v, o);
    __syncthreads();
    if ((threadIdx.x & 31) == 0) red[threadIdx.x >> 5] = v;
    __syncthreads();
    return red[0] + red[1] + red[2] + red[3];
}

__device__ __forceinline__ float blk_max128(float v, float* red) {
    #pragma unroll
    for (int o = 16; o > 0; o >>= 1) v = fmaxf(v, __shfl_down_sync(0xffffffffu, v, o));
    __syncthreads();
    if ((threadIdx.x & 31) == 0) red[threadIdx.x >> 5] = v;
    __syncthreads();
    return fmaxf(fmaxf(red[0], red[1]), fmaxf(red[2], red[3]));
}

// ---------------- kernel 1: adjacency -> neighbor lists ----------------
__global__ void build_graph_kernel(const float* __restrict__ adj) {
    int m = blockIdx.x;
    int l = threadIdx.x;
    float deg = 0.0f;
    int cnt = 0;
    for (int base = 0; base < N_; base += 32) {
        float a = adj[m * N_ + base + l];
        bool nz = (a != 0.0f);
        deg += a;
        unsigned mask = __ballot_sync(0xffffffffu, nz);
        int pre = __popc(mask & ((1u << l) - 1u));
        if (nz) g_nbr[m * N_ + cnt + pre] = base + l;
        cnt += __popc(mask);
    }
    #pragma unroll
    for (int o = 16; o > 0; o >>= 1) deg += __shfl_down_sync(0xffffffffu, deg, o);
    if (l == 0) {
        g_cnt[m] = cnt;
        g_invdeg[m] = 1.0f / (deg + 1e-8f);
    }
}

// ---------------- kernel 2: encoder -> sol[0] + logits[0] ----------------
__global__ __launch_bounds__(128) void encoder_kernel(
    const float* __restrict__ x, const float* __restrict__ enc_w,
    const float* __restrict__ enc_b, const float* __restrict__ enc_g,
    const float* __restrict__ enc_beta,
    const float* __restrict__ attn_w, const float* __restrict__ attn_b)
{
    int row = blockIdx.x;
    int b = row >> 10, n = row & 1023;
    int j = threadIdx.x;
    __shared__ float xr[C_];
    __shared__ float red[4];
    if (j < C_) xr[j] = x[(size_t)b * (S_ * N_ * C_) + (size_t)n * C_ + j];
    __syncthreads();
    float acc = enc_b[j];
    #pragma unroll
    for (int c = 0; c < C_; ++c) acc = fmaf(xr[c], enc_w[c * H_ + j], acc);
    float mean = blk_sum128(acc, red) * (1.0f / H_);
    float d = acc - mean;
    float var = blk_sum128(d * d, red) * (1.0f / H_);
    float yn = d * rsqrtf(var + 1e-5f) * enc_g[j] + enc_beta[j];
    float z = siluf_(yn);
    g_sol[(size_t)row * H_ + j] = z;
    float lgt = blk_sum128(z * attn_w[j], red);
    if (j == 0) g_logits[row] = lgt + attn_b[0];
}

// ---------------- kernel 3: dyn MLP as 64-row register-tiled GEMM ----------------
// grid = 128 blocks/step, 128 threads, 8x8 tile.
__global__ __launch_bounds__(128) void step_dyn_gemm(
    int p,
    const float* __restrict__ w1, const float* __restrict__ b1,
    const float* __restrict__ lgm, const float* __restrict__ lbt,
    const float* __restrict__ w2, const float* __restrict__ b2)
{
    __shared__ float buf[64 * 132];        // Xt [k*64+r] then Hs [r*132+k]
    __shared__ float psum[64 * 16];
    __shared__ float psq[64 * 16];
    __shared__ float s_mean[64];
    __shared__ float s_rstd[64];

    int row0 = blockIdx.x << 6;
    int tid = threadIdx.x;

    // load 64x128 s tile (sanitized), transposed Xt[k][r]
    {
        int r = tid >> 1, c0 = (tid & 1) << 6;
        const float4* pp = (const float4*)(g_sol + (size_t)p * ROWS * H_
                                           + (size_t)(row0 + r) * H_ + c0);
        #pragma unroll
        for (int q = 0; q < 16; ++q) {
            float4 v = pp[q];
            int k = c0 + q * 4;
            buf[(k + 0) * 64 + r] = sanf_(v.x);
            buf[(k + 1) * 64 + r] = sanf_(v.y);
            buf[(k + 2) * 64 + r] = sanf_(v.z);
            buf[(k + 3) * 64 + r] = sanf_(v.w);
        }
    }
    __syncthreads();

    int tx = tid & 15, ty = tid >> 4;
    float acc[8][8];
    {
        float4 bi0 = *(const float4*)(b1 + tx * 8);
        float4 bi1 = *(const float4*)(b1 + tx * 8 + 4);
        #pragma unroll
        for (int i = 0; i < 8; ++i) {
            acc[i][0] = bi0.x; acc[i][1] = bi0.y; acc[i][2] = bi0.z; acc[i][3] = bi0.w;
            acc[i][4] = bi1.x; acc[i][5] = bi1.y; acc[i][6] = bi1.z; acc[i][7] = bi1.w;
        }
    }
    const float4* wv = (const float4*)w1;
    #pragma unroll 4
    for (int k = 0; k < H_; ++k) {
        float4 a0 = *(const float4*)&buf[k * 64 + ty * 8];
        float4 a1 = *(const float4*)&buf[k * 64 + ty * 8 + 4];
        float4 w0 = wv[k * 32 + tx * 2];
        float4 w1v = wv[k * 32 + tx * 2 + 1];
        float av[8] = {a0.x, a0.y, a0.z, a0.w, a1.x, a1.y, a1.z, a1.w};
        float bv[8] = {w0.x, w0.y, w0.z, w0.w, w1v.x, w1v.y, w1v.z, w1v.w};
        #pragma unroll
        for (int i = 0; i < 8; ++i)
            #pragma unroll
            for (int j = 0; j < 8; ++j)
                acc[i][j] = fmaf(av[i], bv[j], acc[i][j]);
    }

    // LN stats
    #pragma unroll
    for (int i = 0; i < 8; ++i) {
        float sm = 0.0f, sq = 0.0f;
        #pragma unroll
        for (int j = 0; j < 8; ++j) { sm += acc[i][j]; sq = fmaf(acc[i][j], acc[i][j], sq); }
        psum[(ty * 8 + i) * 16 + tx] = sm;
        psq [(ty * 8 + i) * 16 + tx] = sq;
    }
    __syncthreads();
    if (tid < 64) {
        float sm = 0.0f, sq = 0.0f;
        #pragma unroll
        for (int t = 0; t < 16; ++t) { sm += psum[tid * 16 + t]; sq += psq[tid * 16 + t]; }
        float mean = sm * (1.0f / H_);
        float var  = fmaxf(sq * (1.0f / H_) - mean * mean, 0.0f);
        s_mean[tid] = mean;
        s_rstd[tid] = rsqrtf(var + 1e-5f);
    }
    __syncthreads();

    // LN + SiLU -> Hs row-major (stride 132)
    {
        float4 g0 = *(const float4*)(lgm + tx * 8);
        float4 g1 = *(const float4*)(lgm + tx * 8 + 4);
        float4 e0 = *(const float4*)(lbt + tx * 8);
        float4 e1 = *(const float4*)(lbt + tx * 8 + 4);
        float gj[8] = {g0.x, g0.y, g0.z, g0.w, g1.x, g1.y, g1.z, g1.w};
        float ej[8] = {e0.x, e0.y, e0.z, e0.w, e1.x, e1.y, e1.z, e1.w};
        __syncthreads();   // all Xt reads done before overwrite
        #pragma unroll
        for (int i = 0; i < 8; ++i) {
            int r = ty * 8 + i;
            float m = s_mean[r], rs = s_rstd[r];
            float hv[8];
            #pragma unroll
            for (int j = 0; j < 8; ++j)
                hv[j] = siluf_((acc[i][j] - m) * rs * gj[j] + ej[j]);
            float4* dst = (float4*)&buf[r * 132 + tx * 8];
            dst[0] = make_float4(hv[0], hv[1], hv[2], hv[3]);
            dst[1] = make_float4(hv[4], hv[5], hv[6], hv[7]);
        }
    }
    __syncthreads();

    // GEMM2: dyn = tanh(Hs @ w2 + b2)
    {
        float4 bi0 = *(const float4*)(b2 + tx * 8);
        float4 bi1 = *(const float4*)(b2 + tx * 8 + 4);
        #pragma unroll
        for (int i = 0; i < 8; ++i) {
            acc[i][0] = bi0.x; acc[i][1] = bi0.y; acc[i][2] = bi0.z; acc[i][3] = bi0.w;
            acc[i][4] = bi1.x; acc[i][5] = bi1.y; acc[i][6] = bi1.z; acc[i][7] = bi1.w;
        }
    }
    const float4* wv2 = (const float4*)w2;
    #pragma unroll 4
    for (int k = 0; k < H_; ++k) {
        float4 w0 = wv2[k * 32 + tx * 2];
        float4 w1v = wv2[k * 32 + tx * 2 + 1];
        float bv[8] = {w0.x, w0.y, w0.z, w0.w, w1v.x, w1v.y, w1v.z, w1v.w};
        float av[8];
        #pragma unroll
        for (int i = 0; i < 8; ++i) av[i] = buf[(ty * 8 + i) * 132 + k];
        #pragma unroll
        for (int i = 0; i < 8; ++i)
            #pragma unroll
            for (int j = 0; j < 8; ++j)
                acc[i][j] = fmaf(av[i], bv[j], acc[i][j]);
    }
    #pragma unroll
    for (int i = 0; i < 8; ++i) {
        float o[8];
        #pragma unroll
        for (int j = 0; j < 8; ++j) o[j] = tanhf(acc[i][j]);
        float4* dst = (float4*)&g_dyn[(size_t)(row0 + ty * 8 + i) * H_ + tx * 8];
        dst[0] = make_float4(o[0], o[1], o[2], o[3]);
        dst[1] = make_float4(o[4], o[5], o[6], o[7]);
    }
}

// ---------------- kernel 4: softmax(in-block) + gather + clamp + update + next logits ----------------
__global__ __launch_bounds__(128) void step_update_kernel(
    int p, const float* __restrict__ diff_scale, const float* __restrict__ time_scale,
    const float* __restrict__ attn_w, const float* __restrict__ attn_b)
{
    int row = blockIdx.x;
    int b = row >> 10, m = row & 1023;
    int j = threadIdx.x;
    __shared__ float attn_sh[N_];
    __shared__ float red[4];

    // per-block softmax over this batch's precomputed logits
    const float* lg = &g_logits[b * N_];
    float lv[8];
    float mloc = -INFINITY;
    #pragma unroll
    for (int i = 0; i < 8; ++i) { lv[i] = lg[j + i * 128]; mloc = fmaxf(mloc, lv[i]); }
    float mx = blk_max128(mloc, red);
    float sloc = 0.0f;
    #pragma unroll
    for (int i = 0; i < 8; ++i) { lv[i] = expf(lv[i] - mx); sloc += lv[i]; }
    float tot = blk_sum128(sloc, red);
    float inv = 1.0f / tot;
    #pragma unroll
    for (int i = 0; i < 8; ++i) attn_sh[j + i * 128] = lv[i] * inv;
    __syncthreads();

    // neighbor gather
    int cnt = g_cnt[m];
    const int* nb = &g_nbr[m * N_];
    const float* sbase = &g_sol[(size_t)p * ROWS * H_ + (size_t)b * N_ * H_];
    float diff = 0.0f;
    for (int i = 0; i < cnt; ++i) {
        int n = nb[i];
        diff = fmaf(sanf_(sbase[(size_t)n * H_ + j]), attn_sh[n], diff);
    }
    diff *= g_invdeg[m] * diff_scale[0];

    float dyn = g_dyn[(size_t)row * H_ + j];
    float dx = time_scale[0] * (dyn + diff);
    float n2 = blk_sum128(dx * dx, red);
    float sc = fminf(10.0f / (sqrtf(n2) + 1e-8f), 1.0f);
    dx = sanf_(dx * sc);

    float snew = g_sol[(size_t)p * ROWS * H_ + (size_t)row * H_ + j] + dx * DT_;
    g_sol[(size_t)(p + 1) * ROWS * H_ + (size_t)row * H_ + j] = snew;

    // logits for next step
    float lgt = blk_sum128(sanf_(snew) * attn_w[j], red);
    if (j == 0) g_logits[row] = lgt + attn_b[0];
}

// ---------------- kernel 5: frame GEMM  Y = sol @ dec_w1 + b1 (all 10 frames) ----------------
// grid = 1280 blocks (81920 rows / 64)
__global__ __launch_bounds__(128) void frame_gemm_kernel(
    const float* __restrict__ w1, const float* __restrict__ b1)
{
    __shared__ float buf[64 * 128];        // Xt[k][r]
    int row0 = blockIdx.x << 6;
    int tid = threadIdx.x;
    {
        int r = tid >> 1, c0 = (tid & 1) << 6;
        const float4* pp = (const float4*)(g_sol + (size_t)(row0 + r) * H_ + c0);
        #pragma unroll
        for (int q = 0; q < 16; ++q) {
            float4 v = pp[q];
            int k = c0 + q * 4;
            buf[(k + 0) * 64 + r] = v.x;
            buf[(k + 1) * 64 + r] = v.y;
            buf[(k + 2) * 64 + r] = v.z;
            buf[(k + 3) * 64 + r] = v.w;
        }
    }
    __syncthreads();

    int tx = tid & 15, ty = tid >> 4;
    float acc[8][8];
    {
        float4 bi0 = *(const float4*)(b1 + tx * 8);
        float4 bi1 = *(const float4*)(b1 + tx * 8 + 4);
        #pragma unroll
        for (int i = 0; i < 8; ++i) {
            acc[i][0] = bi0.x; acc[i][1] = bi0.y; acc[i][2] = bi0.z; acc[i][3] = bi0.w;
            acc[i][4] = bi1.x; acc[i][5] = bi1.y; acc[i][6] = bi1.z; acc[i][7] = bi1.w;
        }
    }
    const float4* wv = (const float4*)w1;
    #pragma unroll 4
    for (int k = 0; k < H_; ++k) {
        float4 a0 = *(const float4*)&buf[k * 64 + ty * 8];
        float4 a1 = *(const float4*)&buf[k * 64 + ty * 8 + 4];
        float4 w0 = wv[k * 32 + tx * 2];
        float4 w1v = wv[k * 32 + tx * 2 + 1];
        float av[8] = {a0.x, a0.y, a0.z, a0.w, a1.x, a1.y, a1.z, a1.w};
        float bv[8] = {w0.x, w0.y, w0.z, w0.w, w1v.x, w1v.y, w1v.z, w1v.w};
        #pragma unroll
        for (int i = 0; i < 8; ++i)
            #pragma unroll
            for (int jj = 0; jj < 8; ++jj)
                acc[i][jj] = fmaf(av[i], bv[jj], acc[i][jj]);
    }
    #pragma unroll
    for (int i = 0; i < 8; ++i) {
        float4* dst = (float4*)&g_y[(size_t)(row0 + ty * 8 + i) * H_ + tx * 8];
        dst[0] = make_float4(acc[i][0], acc[i][1], acc[i][2], acc[i][3]);
        dst[1] = make_float4(acc[i][4], acc[i][5], acc[i][6], acc[i][7]);
    }
}

// ---------------- kernel 6: interp(Y) + LN + SiLU + GEMM2 + outputs ----------------
// grid = 8192 blocks, 64 rows each.
__global__ __launch_bounds__(128) void decoder_interp_kernel(
    const float* __restrict__ lgm, const float* __restrict__ lbt,
    const float* __restrict__ w2, const float* __restrict__ b2,
    float* __restrict__ out_pred, float* __restrict__ out_interp)
{
    __shared__ float buf[64 * 132];
    __shared__ float psum[128], psq[128];
    __shared__ float s_mean[64], s_rstd[64];
    __shared__ float gl[H_], bl[H_];

    int blk = blockIdx.x;
    int tid = threadIdx.x;
    int n0 = (blk & 15) << 6;
    int sb = blk >> 4;
    int b  = sb & 7;
    int s  = sb >> 3;

    gl[tid] = lgm[tid];
    bl[tid] = lbt[tid];

    int ic = (s + 6) / 7;
    if (ic < 1) ic = 1;
    if (ic > P_ - 1) ic = P_ - 1;
    float alpha = (float)(s - 7 * (ic - 1)) * (1.0f / 7.0f);
    float oma = 1.0f - alpha;

    // load + interp Y (and sol for out_interp), LN partials
    {
        int r = tid >> 1, c0 = (tid & 1) << 6;
        size_t rowbase = ((size_t)b * N_ + (n0 + r)) * H_ + c0;
        const float4* y0p = (const float4*)(g_y + (size_t)(ic - 1) * ROWS * H_ + rowbase);
        const float4* y1p = (const float4*)(g_y + (size_t)ic * ROWS * H_ + rowbase);
        float sm = 0.0f, sq = 0.0f;
        #pragma unroll
        for (int q = 0; q < 16; ++q) {
            float4 v0 = y0p[q], v1 = y1p[q];
            float4 yv;
            yv.x = oma * v0.x + alpha * v1.x;
            yv.y = oma * v0.y + alpha * v1.y;
            yv.z = oma * v0.z + alpha * v1.z;
            yv.w = oma * v0.w + alpha * v1.w;
            sm += yv.x + yv.y + yv.z + yv.w;
            sq = fmaf(yv.x, yv.x, sq); sq = fmaf(yv.y, yv.y, sq);
            sq = fmaf(yv.z, yv.z, sq); sq = fmaf(yv.w, yv.w, sq);
            *(float4*)&buf[r * 132 + c0 + q * 4] = yv;
        }
        psum[r * 2 + (tid & 1)] = sm;
        psq [r * 2 + (tid & 1)] = sq;

        if (out_interp) {
            const float4* s0p = (const float4*)(g_sol + (size_t)(ic - 1) * ROWS * H_ + rowbase);
            const float4* s1p = (const float4*)(g_sol + (size_t)ic * ROWS * H_ + rowbase);
            float4* po = (float4*)(out_interp + ((size_t)(s * B_ + b) * N_ + (n0 + r)) * H_ + c0);
            #pragma unroll
            for (int q = 0; q < 16; ++q) {
                float4 v0 = s0p[q], v1 = s1p[q];
                float4 iv;
                iv.x = oma * v0.x + alpha * v1.x;
                iv.y = oma * v0.y + alpha * v1.y;
                iv.z = oma * v0.z + alpha * v1.z;
                iv.w = oma * v0.w + alpha * v1.w;
                po[q] = iv;
            }
        }
    }
    __syncthreads();

    if (tid < 64) {
        float sm = psum[tid * 2] + psum[tid * 2 + 1];
        float sq = psq[tid * 2] + psq[tid * 2 + 1];
        float mean = sm * (1.0f / H_);
        float var  = fmaxf(sq * (1.0f / H_) - mean * mean, 0.0f);
        s_mean[tid] = mean;
        s_rstd[tid] = rsqrtf(var + 1e-5f);
    }
    __syncthreads();

    // LN + SiLU in place
    {
        int r = tid >> 1, c0 = (tid & 1) << 6;
        float m = s_mean[r], rs = s_rstd[r];
        #pragma unroll
        for (int q = 0; q < 16; ++q) {
            int k = c0 + q * 4;
            float4 yv = *(float4*)&buf[r * 132 + k];
            yv.x = siluf_((yv.x - m) * rs * gl[k + 0] + bl[k + 0]);
            yv.y = siluf_((yv.y - m) * rs * gl[k + 1] + bl[k + 1]);
            yv.z = siluf_((yv.z - m) * rs * gl[k + 2] + bl[k + 2]);
            yv.w = siluf_((yv.w - m) * rs * gl[k + 3] + bl[k + 3]);
            *(float4*)&buf[r * 132 + k] = yv;
        }
    }
    __syncthreads();

    // GEMM2: pred[64 x 16]
    if (out_pred) {
        int c0 = (tid & 3) * 4;
        int rg = tid >> 2;
        float4 bb = *(const float4*)(b2 + c0);
        float acc2[2][4];
        #pragma unroll
        for (int r = 0; r < 2; ++r) {
            acc2[r][0] = bb.x; acc2[r][1] = bb.y; acc2[r][2] = bb.z; acc2[r][3] = bb.w;
        }
        #pragma unroll 4
        for (int k4 = 0; k4 < 32; ++k4) {
            int k = k4 * 4;
            float4 wr0 = *(const float4*)(w2 + (k + 0) * C_ + c0);
            float4 wr1 = *(const float4*)(w2 + (k + 1) * C_ + c0);
            float4 wr2 = *(const float4*)(w2 + (k + 2) * C_ + c0);
            float4 wr3 = *(const float4*)(w2 + (k + 3) * C_ + c0);
            #pragma unroll
            for (int r = 0; r < 2; ++r) {
                float4 av = *(const float4*)&buf[(rg * 2 + r) * 132 + k];
                acc2[r][0] = fmaf(av.x, wr0.x, acc2[r][0]);
                acc2[r][1] = fmaf(av.x, wr0.y, acc2[r][1]);
                acc2[r][2] = fmaf(av.x, wr0.z, acc2[r][2]);
                acc2[r][3] = fmaf(av.x, wr0.w, acc2[r][3]);
                acc2[r][0] = fmaf(av.y, wr1.x, acc2[r][0]);
                acc2[r][1] = fmaf(av.y, wr1.y, acc2[r][1]);
                acc2[r][2] = fmaf(av.y, wr1.z, acc2[r][2]);
                acc2[r][3] = fmaf(av.y, wr1.w, acc2[r][3]);
                acc2[r][0] = fmaf(av.z, wr2.x, acc2[r][0]);
                acc2[r][1] = fmaf(av.z, wr2.y, acc2[r][1]);
                acc2[r][2] = fmaf(av.z, wr2.z, acc2[r][2]);
                acc2[r][3] = fmaf(av.z, wr2.w, acc2[r][3]);
                acc2[r][0] = fmaf(av.w, wr3.x, acc2[r][0]);
                acc2[r][1] = fmaf(av.w, wr3.y, acc2[r][1]);
                acc2[r][2] = fmaf(av.w, wr3.z, acc2[r][2]);
                acc2[r][3] = fmaf(av.w, wr3.w, acc2[r][3]);
            }
        }
        #pragma unroll
        for (int r = 0; r < 2; ++r) {
            int n = n0 + rg * 2 + r;
            float4* dst = (float4*)&out_pred[(((size_t)b * S_ + s) * N_ + n) * C_ + c0];
            *dst = make_float4(acc2[r][0], acc2[r][1], acc2[r][2], acc2[r][3]);
        }
    }
}

// ---------------- launch ----------------
extern "C" void kernel_launch(void* const* d_in, const int* in_sizes, int n_in,
                              void* d_out, int out_size)
{
    const float* x        = (const float*)d_in[0];
    const float* adj      = (const float*)d_in[1];
    const float* enc_w    = (const float*)d_in[2];
    const float* enc_b    = (const float*)d_in[3];
    const float* enc_g    = (const float*)d_in[4];
    const float* enc_beta = (const float*)d_in[5];
    const float* dyn_w1   = (const float*)d_in[6];
    const float* dyn_b1   = (const float*)d_in[7];
    const float* dyn_g    = (const float*)d_in[8];
    const float* dyn_beta = (const float*)d_in[9];
    const float* dyn_w2   = (const float*)d_in[10];
    const float* dyn_b2   = (const float*)d_in[11];
    const float* attn_w   = (const float*)d_in[12];
    const float* attn_b   = (const float*)d_in[13];
    const float* diff_sc  = (const float*)d_in[14];
    const float* time_sc  = (const float*)d_in[15];
    const float* dec_w1   = (const float*)d_in[16];
    const float* dec_b1   = (const float*)d_in[17];
    const float* dec_g    = (const float*)d_in[18];
    const float* dec_beta = (const float*)d_in[19];
    const float* dec_w2   = (const float*)d_in[20];
    const float* dec_b2   = (const float*)d_in[21];

    float* out = (float*)d_out;
    float* out_pred = nullptr;
    float* out_interp = nullptr;
    if (out_size >= PRED_ELEMS + INTERP_ELEMS) {
        out_pred = out;
        out_interp = out + PRED_ELEMS;
    } else if (out_size == PRED_ELEMS) {
        out_pred = out;
    } else if (out_size == INTERP_ELEMS) {
        out_interp = out;
    } else {
        out_pred = out;
    }

    build_graph_kernel<<<N_, 32>>>(adj);
    encoder_kernel<<<ROWS, 128>>>(x, enc_w, enc_b, enc_g, enc_beta, attn_w, attn_b);

    for (int p = 0; p < P_ - 1; ++p) {
        step_dyn_gemm<<<ROWS / 64, 128>>>(p, dyn_w1, dyn_b1, dyn_g, dyn_beta,
                                          dyn_w2, dyn_b2);
        step_update_kernel<<<ROWS, 128>>>(p, diff_sc, time_sc, attn_w, attn_b);
    }

    frame_gemm_kernel<<<P_ * ROWS / 64, 128>>>(dec_w1, dec_b1);
    decoder_interp_kernel<<<S_ * B_ * N_ / 64, 128>>>(dec_g, dec_beta, dec_w2, dec_b2,
                                                      out_pred, out_interp);
}